// round 1
// baseline (speedup 1.0000x reference)
#include <cuda_runtime.h>

// GAT layer, N=8192, Fin=128, Fout=64.
// inputs (metadata order): x [N,128] f32, adj [N,N] f32, W [128,64] f32, a [128,1] f32
// output: [N,64] f32

#define N    8192
#define FIN  128
#define FOUT 64
#define TI   128      // output rows per block (== blockDim)
#define TJ   32       // j-tile
#define JSPLIT 8
#define JRANGE (N / JSPLIT)   // 1024

// ---- device scratch (no allocation allowed) ----
__device__ float g_Wh[N * FOUT];                 // 2 MB
__device__ float g_E1[N], g_E1b[N];              // exp(Wh1), exp(0.2*Wh1)
__device__ float g_E2[N], g_E2b[N];              // exp(Wh2), exp(0.2*Wh2)
__device__ float g_acc[JSPLIT][N * FOUT];        // 16 MB partial numerators
__device__ float g_den[JSPLIT][N];               // partial denominators

// ============================================================
// Kernel A: Wh = x@W ; Wh1 = Wh@a[:64]; Wh2 = Wh@a[64:]; exp tables
// 128 blocks x 256 threads; 64 rows/block, 4 threads/row (16 cols each)
// ============================================================
__global__ void __launch_bounds__(256) gat_prep(const float* __restrict__ x,
                                                const float* __restrict__ W,
                                                const float* __restrict__ a)
{
    __shared__ float wS[FIN][FOUT];
    int t = threadIdx.x;
    #pragma unroll
    for (int q = 0; q < (FIN * FOUT) / 256; q++) {
        int idx = q * 256 + t;
        wS[idx >> 6][idx & 63] = W[idx];
    }
    __syncthreads();

    int row = blockIdx.x * 64 + (t >> 2);
    int seg = t & 3;                       // column segment: seg*16 .. seg*16+15
    const float* xr = x + (size_t)row * FIN;

    float acc[16];
    #pragma unroll
    for (int f = 0; f < 16; f++) acc[f] = 0.f;

    for (int kk = 0; kk < FIN; kk++) {
        float xv = xr[kk];
        #pragma unroll
        for (int f = 0; f < 16; f++) acc[f] += xv * wS[kk][seg * 16 + f];
    }

    float* whr = g_Wh + (size_t)row * FOUT + seg * 16;
    #pragma unroll
    for (int f = 0; f < 16; f++) whr[f] = acc[f];

    float p1 = 0.f, p2 = 0.f;
    #pragma unroll
    for (int f = 0; f < 16; f++) {
        p1 += acc[f] * a[seg * 16 + f];
        p2 += acc[f] * a[FOUT + seg * 16 + f];
    }
    // reduce over the 4 consecutive lanes that share a row
    p1 += __shfl_xor_sync(0xffffffffu, p1, 1);
    p1 += __shfl_xor_sync(0xffffffffu, p1, 2);
    p2 += __shfl_xor_sync(0xffffffffu, p2, 1);
    p2 += __shfl_xor_sync(0xffffffffu, p2, 2);

    if (seg == 0) {
        g_E1 [row] = __expf(p1);
        g_E1b[row] = __expf(0.2f * p1);
        g_E2 [row] = __expf(p2);
        g_E2b[row] = __expf(0.2f * p2);
    }
}

// ============================================================
// Kernel B: fused masked-softmax-numerator + (attn @ Wh) partials.
// grid (N/TI, JSPLIT) = (64, 8) blocks of TI=128 threads.
// Thread t owns output row i = blockIdx.x*TI + t:
//   den  = sum_j p_ij
//   acc  = sum_j p_ij * Wh[j]   (64 floats as 32 packed f32x2)
// p_ij = adj>0 ? (e1*e2[j] > 1 ? e1*e2[j] : e1b*e2b[j]) : 0
// (exp(leaky_relu(c)) factorized; branch test e^c>1 <=> c>0)
// ============================================================
__global__ void __launch_bounds__(TI) gat_attn(const float* __restrict__ adj)
{
    __shared__ __align__(16) float adjS[TI][TJ + 1];   // +1 pad: conflict-free column reads
    __shared__ __align__(16) float whS[TJ][FOUT];
    __shared__ float e2S[TJ], e2bS[TJ];

    int t  = threadIdx.x;
    int ib = blockIdx.x;
    int js = blockIdx.y;
    int i  = ib * TI + t;

    float e1  = g_E1[i];
    float e1b = g_E1b[i];

    unsigned long long acc[FOUT / 2];
    #pragma unroll
    for (int f = 0; f < FOUT / 2; f++) acc[f] = 0ULL;
    float den = 0.f;

    const int j0 = js * JRANGE;
    for (int jt = j0; jt < j0 + JRANGE; jt += TJ) {
        __syncthreads();
        // adj tile: TI x TJ, fully coalesced (each warp reads one 128B row-segment)
        #pragma unroll
        for (int q = 0; q < TJ; q++) {
            int idx = q * TI + t;
            int r = idx >> 5, c = idx & 31;
            adjS[r][c] = adj[(size_t)(ib * TI + r) * N + jt + c];
        }
        // Wh tile: TJ x 64
        #pragma unroll
        for (int q = 0; q < (TJ * FOUT) / TI; q++) {
            int idx = q * TI + t;
            int jr = idx >> 6, f = idx & 63;
            whS[jr][f] = g_Wh[(size_t)(jt + jr) * FOUT + f];
        }
        if (t < TJ) { e2S[t] = g_E2[jt + t]; e2bS[t] = g_E2b[jt + t]; }
        __syncthreads();

        #pragma unroll 1
        for (int jj = 0; jj < TJ; jj++) {
            float av  = adjS[t][jj];
            float pp1 = e1  * e2S[jj];
            float pp2 = e1b * e2bS[jj];
            float p   = (pp1 > 1.f) ? pp1 : pp2;     // leaky_relu branch
            p = (av > 0.f) ? p : 0.f;                // adjacency mask
            den += p;

            unsigned long long pk;
            asm("mov.b64 %0, {%1, %2};" : "=l"(pk) : "f"(p), "f"(p));
            const unsigned long long* w64 =
                reinterpret_cast<const unsigned long long*>(&whS[jj][0]);
            #pragma unroll
            for (int f = 0; f < FOUT / 2; f++) {
                // packed dual-fp32 FMA: 2x FFMA throughput vs scalar
                asm("fma.rn.f32x2 %0, %1, %2, %3;"
                    : "=l"(acc[f]) : "l"(pk), "l"(w64[f]), "l"(acc[f]));
            }
        }
    }

    unsigned long long* aout =
        reinterpret_cast<unsigned long long*>(&g_acc[js][(size_t)i * FOUT]);
    #pragma unroll
    for (int f = 0; f < FOUT / 2; f++) aout[f] = acc[f];
    g_den[js][i] = den;
}

// ============================================================
// Kernel C: combine partials, normalize, ELU.
// ============================================================
__global__ void __launch_bounds__(256) gat_final(float* __restrict__ out)
{
    int idx = blockIdx.x * 256 + threadIdx.x;   // < N*FOUT
    int i = idx >> 6;
    float d = 0.f, v = 0.f;
    #pragma unroll
    for (int s = 0; s < JSPLIT; s++) {
        d += g_den[s][i];
        v += g_acc[s][idx];
    }
    float h = v / d;
    out[idx] = (h > 0.f) ? h : expm1f(h);
}

// ============================================================
extern "C" void kernel_launch(void* const* d_in, const int* in_sizes, int n_in,
                              void* d_out, int out_size)
{
    const float* x   = (const float*)d_in[0];
    const float* adj = (const float*)d_in[1];
    const float* W   = (const float*)d_in[2];
    const float* a   = (const float*)d_in[3];
    float* out = (float*)d_out;

    gat_prep<<<N / 64, 256>>>(x, W, a);
    gat_attn<<<dim3(N / TI, JSPLIT), TI>>>(adj);
    gat_final<<<(N * FOUT) / 256, 256>>>(out);
}

// round 2
// speedup vs baseline: 1.2285x; 1.2285x over previous
#include <cuda_runtime.h>
#include <cstdint>

// GAT layer, N=8192, Fin=128, Fout=64.
// inputs: x [N,128] f32, adj [N,N] f32 (0/1), W [128,64] f32, a [128,1] f32
// output: [N,64] f32

#define N      8192
#define FOUT   64
#define TI     256
#define TJ     32
#define JSPLIT 16
#define JRANGE (N / JSPLIT)     // 512
#define NT     (JRANGE / TJ)    // 16 tiles per block

// ---------------- device scratch ----------------
__device__ float2 g_E1P[N];               // (e^Wh1, e^{0.2 Wh1})
__device__ float2 g_E2P[N];               // (e^Wh2, e^{0.2 Wh2})
__device__ float  g_WhD[N * 160];         // Wh duplicated: row j = 8 chunks of 16 floats (w,w pairs) + 4 pad floats, stride 160
__device__ float  g_acc[JSPLIT][N * FOUT];// pair-interleaved partial numerators
__device__ float  g_den[JSPLIT][N];       // partial denominators

// ---------------- helpers ----------------
__device__ __forceinline__ unsigned long long packdup(float v) {
    unsigned long long r;
    asm("mov.b64 %0, {%1, %1};" : "=l"(r) : "f"(v));
    return r;
}
__device__ __forceinline__ float2 unpack2(unsigned long long v) {
    float2 r;
    asm("mov.b64 {%0, %1}, %2;" : "=f"(r.x), "=f"(r.y) : "l"(v));
    return r;
}
#define FFMA2(d, a, b) asm("fma.rn.f32x2 %0, %1, %2, %3;" : "=l"(d) : "l"(a), "l"(b), "l"(d))

#define CP_ASYNC16(dst, src) \
    asm volatile("cp.async.cg.shared.global [%0], [%1], 16;" :: "r"(dst), "l"(src))
#define CP_COMMIT() asm volatile("cp.async.commit_group;")
#define CP_WAIT0()  asm volatile("cp.async.wait_group 0;" ::: "memory")

// ============================================================
// Kernel A: Wh = x@W (FFMA2), Wh1/Wh2 dots, exp tables, duplicated-Wh store.
// 256 blocks x 256 threads; 32 rows/block, 8 threads/row (8 cols each).
// ============================================================
__global__ void __launch_bounds__(256) gat_prep(const float* __restrict__ x,
                                                const float* __restrict__ W,
                                                const float* __restrict__ a)
{
    __shared__ float wS[128 * 64];
    __shared__ float aS[128];
    const int t = threadIdx.x;

    #pragma unroll
    for (int q = 0; q < 8; q++) {
        int idx = (q * 256 + t) * 4;
        *(float4*)&wS[idx] = *(const float4*)&W[idx];
    }
    if (t < 32) *(float4*)&aS[t * 4] = *(const float4*)&a[t * 4];
    __syncthreads();

    const int row = blockIdx.x * 32 + (t >> 3);
    const int tx  = t & 7;
    const float* xr = x + (size_t)row * 128;

    unsigned long long acc4[4] = {0ull, 0ull, 0ull, 0ull};

    #pragma unroll 16
    for (int kk = 0; kk < 128; kk++) {
        unsigned long long xd = packdup(xr[kk]);
        const unsigned long long* w =
            reinterpret_cast<const unsigned long long*>(&wS[kk * 64 + tx * 8]);
        FFMA2(acc4[0], xd, w[0]);
        FFMA2(acc4[1], xd, w[1]);
        FFMA2(acc4[2], xd, w[2]);
        FFMA2(acc4[3], xd, w[3]);
    }

    float wv[8];
    #pragma unroll
    for (int m = 0; m < 4; m++) {
        float2 u = unpack2(acc4[m]);
        wv[2 * m] = u.x; wv[2 * m + 1] = u.y;
    }

    float p1 = 0.f, p2 = 0.f;
    #pragma unroll
    for (int c = 0; c < 8; c++) {
        p1 += wv[c] * aS[tx * 8 + c];
        p2 += wv[c] * aS[64 + tx * 8 + c];
    }
    p1 += __shfl_xor_sync(0xffffffffu, p1, 1);
    p1 += __shfl_xor_sync(0xffffffffu, p1, 2);
    p1 += __shfl_xor_sync(0xffffffffu, p1, 4);
    p2 += __shfl_xor_sync(0xffffffffu, p2, 1);
    p2 += __shfl_xor_sync(0xffffffffu, p2, 2);
    p2 += __shfl_xor_sync(0xffffffffu, p2, 4);

    // duplicated Wh: chunk tx at row*160 + tx*20, 4 float4 of (w,w,w',w')
    float* dst = g_WhD + (size_t)row * 160 + tx * 20;
    #pragma unroll
    for (int m = 0; m < 4; m++) {
        *(float4*)&dst[m * 4] =
            make_float4(wv[2 * m], wv[2 * m], wv[2 * m + 1], wv[2 * m + 1]);
    }

    if (tx == 0) {
        g_E1P[row] = make_float2(__expf(p1), __expf(0.2f * p1));
        g_E2P[row] = make_float2(__expf(p2), __expf(0.2f * p2));
    }
}

// ============================================================
// Kernel B: fused P-build + register-tiled GEMM.
// grid (N/TI, JSPLIT) = (32, 16), 256 threads.
// Dynamic smem layout (floats):
//   adjS : [256][36]        ( 9216 f, 36864 B)
//   P_T  : [32][260]        ( 8320 f, 33280 B)
//   whD  : [2][32][160]     (10240 f, 40960 B)
//   e2p  : [2][32] float2   (  128 f,   512 B)
// total 111616 B
// ============================================================
#define SM_ADJ  0
#define SM_PT   9216
#define SM_WHD  (9216 + 8320)
#define SM_E2   (9216 + 8320 + 10240)
#define SMEMB_BYTES 111616

extern __shared__ float smemB[];

__global__ void __launch_bounds__(256, 2) gat_attn(const float* __restrict__ adj)
{
    float* adjS = smemB + SM_ADJ;
    float* P_T  = smemB + SM_PT;
    float* whD  = smemB + SM_WHD;
    float2* e2p = (float2*)(smemB + SM_E2);

    const int t  = threadIdx.x;
    const int ib = blockIdx.x;
    const int js = blockIdx.y;
    const int i_base = ib * TI;
    const int j0 = js * JRANGE;

    const int tx = t & 7;        // GEMM col chunk (8 cols)
    const int ty = t >> 3;       // GEMM row group (8 rows)
    const int rg = t >> 2;       // P-build row group (4 rows)
    const int cg = t & 3;        // P-build col group (8 cols)

    uint32_t s_adj = (uint32_t)__cvta_generic_to_shared(adjS);
    uint32_t s_whd = (uint32_t)__cvta_generic_to_shared(whD);
    uint32_t s_e2  = (uint32_t)__cvta_generic_to_shared(e2p);

    float2 e1p[4];
    #pragma unroll
    for (int k = 0; k < 4; k++) e1p[k] = g_E1P[i_base + rg * 4 + k];

    float den4[4] = {0.f, 0.f, 0.f, 0.f};
    unsigned long long acc[4][8];
    #pragma unroll
    for (int r = 0; r < 4; r++)
        #pragma unroll
        for (int c = 0; c < 8; c++) acc[r][c] = 0ull;

    const float* adj_row = adj + (size_t)(i_base + t) * N + j0;

    // ---- prologue: prefetch tile 0 into buffer 0 ----
    {
        uint32_t ad = s_adj + t * 144;
        #pragma unroll
        for (int m = 0; m < 8; m++) CP_ASYNC16(ad + m * 16, adj_row + m * 4);
        const float* ws = g_WhD + (size_t)j0 * 160 + t * 20;
        uint32_t wd = s_whd + t * 80;
        #pragma unroll
        for (int m = 0; m < 5; m++) CP_ASYNC16(wd + m * 16, ws + m * 4);
        if (t < 16)
            CP_ASYNC16(s_e2 + t * 16, (const float*)(g_E2P + j0) + t * 4);
        CP_COMMIT();
    }

    for (int it = 0; it < NT; it++) {
        const int pb = it & 1;
        CP_WAIT0();
        __syncthreads();

        // ---- P build: p = max(e1*e2, e1b*e2b) * adj ----
        {
            float4 a4[4][2];
            #pragma unroll
            for (int k = 0; k < 4; k++) {
                #pragma unroll
                for (int m = 0; m < 2; m++)
                    a4[k][m] = *(float4*)&adjS[(rg * 4 + k) * 36 + cg * 8 + m * 4];
            }
            #pragma unroll
            for (int cc = 0; cc < 8; cc++) {
                float2 e2 = e2p[pb * 32 + cg * 8 + cc];
                float p[4];
                #pragma unroll
                for (int k = 0; k < 4; k++) {
                    float pp1 = e1p[k].x * e2.x;
                    float pp2 = e1p[k].y * e2.y;
                    const float* av = (const float*)&a4[k][cc >> 2];
                    p[k] = fmaxf(pp1, pp2) * av[cc & 3];
                    den4[k] += p[k];
                }
                *(float4*)&P_T[(cg * 8 + cc) * 260 + rg * 4] =
                    make_float4(p[0], p[1], p[2], p[3]);
            }
        }
        __syncthreads();

        // ---- prefetch next tile ----
        if (it + 1 < NT) {
            const int jt_n = j0 + (it + 1) * TJ;
            uint32_t ad = s_adj + t * 144;
            const float* asrc = adj_row + (it + 1) * TJ;
            #pragma unroll
            for (int m = 0; m < 8; m++) CP_ASYNC16(ad + m * 16, asrc + m * 4);
            const float* ws = g_WhD + (size_t)jt_n * 160 + t * 20;
            uint32_t wd = s_whd + (pb ^ 1) * 20480 + t * 80;
            #pragma unroll
            for (int m = 0; m < 5; m++) CP_ASYNC16(wd + m * 16, ws + m * 4);
            if (t < 16)
                CP_ASYNC16(s_e2 + (pb ^ 1) * 256 + t * 16,
                           (const float*)(g_E2P + jt_n) + t * 4);
            CP_COMMIT();
        }

        // ---- GEMM: acc[rp][c] += Ppair * WhDup ----
        const float* whb = whD + pb * 5120;
        #pragma unroll
        for (int jj = 0; jj < TJ; jj++) {
            ulonglong2 pA = *(ulonglong2*)&P_T[jj * 260 + ty * 8];
            ulonglong2 pB = *(ulonglong2*)&P_T[jj * 260 + ty * 8 + 4];
            ulonglong2 w0 = *(ulonglong2*)&whb[jj * 160 + tx * 20];
            ulonglong2 w1 = *(ulonglong2*)&whb[jj * 160 + tx * 20 + 4];
            ulonglong2 w2 = *(ulonglong2*)&whb[jj * 160 + tx * 20 + 8];
            ulonglong2 w3 = *(ulonglong2*)&whb[jj * 160 + tx * 20 + 12];

            FFMA2(acc[0][0], pA.x, w0.x); FFMA2(acc[0][1], pA.x, w0.y);
            FFMA2(acc[0][2], pA.x, w1.x); FFMA2(acc[0][3], pA.x, w1.y);
            FFMA2(acc[0][4], pA.x, w2.x); FFMA2(acc[0][5], pA.x, w2.y);
            FFMA2(acc[0][6], pA.x, w3.x); FFMA2(acc[0][7], pA.x, w3.y);

            FFMA2(acc[1][0], pA.y, w0.x); FFMA2(acc[1][1], pA.y, w0.y);
            FFMA2(acc[1][2], pA.y, w1.x); FFMA2(acc[1][3], pA.y, w1.y);
            FFMA2(acc[1][4], pA.y, w2.x); FFMA2(acc[1][5], pA.y, w2.y);
            FFMA2(acc[1][6], pA.y, w3.x); FFMA2(acc[1][7], pA.y, w3.y);

            FFMA2(acc[2][0], pB.x, w0.x); FFMA2(acc[2][1], pB.x, w0.y);
            FFMA2(acc[2][2], pB.x, w1.x); FFMA2(acc[2][3], pB.x, w1.y);
            FFMA2(acc[2][4], pB.x, w2.x); FFMA2(acc[2][5], pB.x, w2.y);
            FFMA2(acc[2][6], pB.x, w3.x); FFMA2(acc[2][7], pB.x, w3.y);

            FFMA2(acc[3][0], pB.y, w0.x); FFMA2(acc[3][1], pB.y, w0.y);
            FFMA2(acc[3][2], pB.y, w1.x); FFMA2(acc[3][3], pB.y, w1.y);
            FFMA2(acc[3][4], pB.y, w2.x); FFMA2(acc[3][5], pB.y, w2.y);
            FFMA2(acc[3][6], pB.y, w3.x); FFMA2(acc[3][7], pB.y, w3.y);
        }
    }

    // ---- epilogue: write pair-interleaved partials ----
    {
        float* ob = g_acc[js];
        const int ip0 = (i_base + ty * 8) >> 1;
        #pragma unroll
        for (int rp = 0; rp < 4; rp++) {
            float* orow = ob + (size_t)(ip0 + rp) * 128 + tx * 16;
            #pragma unroll
            for (int cp = 0; cp < 4; cp++) {
                float2 u0 = unpack2(acc[rp][2 * cp]);
                float2 u1 = unpack2(acc[rp][2 * cp + 1]);
                *(float4*)&orow[cp * 4] = make_float4(u0.x, u0.y, u1.x, u1.y);
            }
        }
    }
    #pragma unroll
    for (int k = 0; k < 4; k++) {
        den4[k] += __shfl_xor_sync(0xffffffffu, den4[k], 1);
        den4[k] += __shfl_xor_sync(0xffffffffu, den4[k], 2);
    }
    if (cg == 0) {
        #pragma unroll
        for (int k = 0; k < 4; k++)
            g_den[js][i_base + rg * 4 + k] = den4[k];
    }
}

// ============================================================
// Kernel C: combine partials, normalize, ELU.
// ============================================================
__global__ void __launch_bounds__(256) gat_final(float* __restrict__ out)
{
    const int idx = blockIdx.x * 256 + threadIdx.x;
    const int i = idx >> 6;
    const int c = idx & 63;
    const int pidx = (i >> 1) * 128 + c * 2 + (i & 1);
    float d = 0.f, v = 0.f;
    #pragma unroll
    for (int s = 0; s < JSPLIT; s++) {
        d += g_den[s][i];
        v += g_acc[s][pidx];
    }
    float h = v / d;
    out[idx] = (h > 0.f) ? h : expm1f(h);
}

// ============================================================
extern "C" void kernel_launch(void* const* d_in, const int* in_sizes, int n_in,
                              void* d_out, int out_size)
{
    const float* x   = (const float*)d_in[0];
    const float* adj = (const float*)d_in[1];
    const float* W   = (const float*)d_in[2];
    const float* a   = (const float*)d_in[3];
    float* out = (float*)d_out;

    cudaFuncSetAttribute(gat_attn, cudaFuncAttributeMaxDynamicSharedMemorySize,
                         SMEMB_BYTES);

    gat_prep<<<N / 32, 256>>>(x, W, a);
    gat_attn<<<dim3(N / TI, JSPLIT), 256, SMEMB_BYTES>>>(adj);
    gat_final<<<(N * FOUT) / 256, 256>>>(out);
}

// round 3
// speedup vs baseline: 2.6020x; 2.1181x over previous
#include <cuda_runtime.h>
#include <cstdint>

// GAT layer, N=8192, Fin=128, Fout=64.
// inputs: x [N,128] f32, adj [N,N] f32 (0/1), W [128,64] f32, a [128,1] f32
// output: [N,64] f32

#define N      8192
#define FOUT   64
#define TI     256
#define TJ     32
#define JSPLIT 16
#define JRANGE (N / JSPLIT)     // 512
#define NT     (JRANGE / TJ)    // 16

// ---------------- device scratch ----------------
__device__ float2 g_E1P[N];               // (e^Wh1, e^{0.2 Wh1})
__device__ float2 g_E2P[N];               // (e^Wh2, e^{0.2 Wh2})
__device__ float  g_WhT[FOUT * N];        // Wh transposed [f][j], tf32-rounded
__device__ float  g_acc[JSPLIT][FOUT * N];// partial numerators, [js][f][i]
__device__ float  g_den[JSPLIT][N];       // partial denominators

// ---------------- helpers ----------------
__device__ __forceinline__ unsigned long long packdup(float v) {
    unsigned long long r;
    asm("mov.b64 %0, {%1, %1};" : "=l"(r) : "f"(v));
    return r;
}
__device__ __forceinline__ float2 unpack2(unsigned long long v) {
    float2 r;
    asm("mov.b64 {%0, %1}, %2;" : "=f"(r.x), "=f"(r.y) : "l"(v));
    return r;
}
#define FFMA2(d, a, b) asm("fma.rn.f32x2 %0, %1, %2, %3;" : "=l"(d) : "l"(a), "l"(b), "l"(d))

// round-to-nearest tf32 (13 low mantissa bits dropped), integer pipe
__device__ __forceinline__ float tf32r(float x) {
    uint32_t u = __float_as_uint(x);
    u = (u + 0x1000u) & 0xFFFFE000u;
    return __uint_as_float(u);
}

#define CP_ASYNC16(dst, src) \
    asm volatile("cp.async.cg.shared.global [%0], [%1], 16;" :: "r"(dst), "l"(src))
#define CP_COMMIT() asm volatile("cp.async.commit_group;")
#define CP_WAIT0()  asm volatile("cp.async.wait_group 0;" ::: "memory")

#define MMA_TF32(D, A0, A1, A2, A3, B0, B1)                                   \
    asm("mma.sync.aligned.m16n8k8.row.col.f32.tf32.tf32.f32 "                 \
        "{%0,%1,%2,%3},{%4,%5,%6,%7},{%8,%9},{%0,%1,%2,%3};"                  \
        : "+f"((D)[0]), "+f"((D)[1]), "+f"((D)[2]), "+f"((D)[3])              \
        : "r"(A0), "r"(A1), "r"(A2), "r"(A3), "r"(B0), "r"(B1))

// ============================================================
// Kernel A: Wh = x@W, Wh1/Wh2 dots, exp tables, transposed tf32 Wh.
// 512 blocks x 256 threads; 16 rows/block, 16 threads/row (4 cols each).
// ============================================================
__global__ void __launch_bounds__(256) gat_prep(const float* __restrict__ x,
                                                const float* __restrict__ W,
                                                const float* __restrict__ a)
{
    __shared__ float wS[128 * 64];
    __shared__ float xS[16 * 128];
    __shared__ float aS[128];
    const int t = threadIdx.x;
    const int row0 = blockIdx.x * 16;

    #pragma unroll
    for (int q = 0; q < 8; q++) {
        int idx = (q * 256 + t) * 4;
        *(float4*)&wS[idx] = *(const float4*)&W[idx];
    }
    if (t < 32) *(float4*)&aS[t * 4] = *(const float4*)&a[t * 4];
    #pragma unroll
    for (int q = 0; q < 2; q++) {
        int idx = (q * 256 + t) * 4;
        *(float4*)&xS[idx] = *(const float4*)&x[(size_t)row0 * 128 + idx];
    }
    __syncthreads();

    const int r = t >> 4, c = t & 15;
    unsigned long long acc2[2] = {0ull, 0ull};

    #pragma unroll 16
    for (int kk = 0; kk < 128; kk++) {
        unsigned long long xd = packdup(xS[r * 128 + kk]);
        const unsigned long long* w =
            reinterpret_cast<const unsigned long long*>(&wS[kk * 64 + c * 4]);
        FFMA2(acc2[0], xd, w[0]);
        FFMA2(acc2[1], xd, w[1]);
    }

    float wv[4];
    { float2 u0 = unpack2(acc2[0]), u1 = unpack2(acc2[1]);
      wv[0] = u0.x; wv[1] = u0.y; wv[2] = u1.x; wv[3] = u1.y; }

    float p1 = 0.f, p2 = 0.f;
    #pragma unroll
    for (int e = 0; e < 4; e++) {
        p1 += wv[e] * aS[c * 4 + e];
        p2 += wv[e] * aS[64 + c * 4 + e];
    }
    p1 += __shfl_xor_sync(0xffffffffu, p1, 1);
    p1 += __shfl_xor_sync(0xffffffffu, p1, 2);
    p1 += __shfl_xor_sync(0xffffffffu, p1, 4);
    p1 += __shfl_xor_sync(0xffffffffu, p1, 8);
    p2 += __shfl_xor_sync(0xffffffffu, p2, 1);
    p2 += __shfl_xor_sync(0xffffffffu, p2, 2);
    p2 += __shfl_xor_sync(0xffffffffu, p2, 4);
    p2 += __shfl_xor_sync(0xffffffffu, p2, 8);

    const int row = row0 + r;
    #pragma unroll
    for (int e = 0; e < 4; e++)
        g_WhT[(size_t)(c * 4 + e) * N + row] = tf32r(wv[e]);

    if (c == 0) {
        g_E1P[row] = make_float2(__expf(p1), __expf(0.2f * p1));
        g_E2P[row] = make_float2(__expf(p2), __expf(0.2f * p2));
    }
}

// ============================================================
// Kernel B: fused P-build + tf32 tensor-core GEMM.
// grid (32, 16) = 512 blocks x 256 threads (8 warps).
// Warp w computes D[f=0..63][i = w*32..w*32+31] for its i-slice.
// Smem (floats):
//   adjS [256][36] @0       (36864 B)
//   P_T  [256][36] @9216    (36864 B)  -- tf32-rounded P, [i][j]
//   whT  [2][64][36] @18432 (18432 B)  -- tf32 Wh^T tile, double-buffered
//   e2S  [32] float2 @23040 (  256 B)
// ============================================================
#define SM_PT   9216
#define SM_WHT  18432
#define SM_E2   23040
#define SMEMB_BYTES ((SM_E2 + 64) * 4)   // 92416

__global__ void __launch_bounds__(256, 2) gat_attn(const float* __restrict__ adj)
{
    extern __shared__ float sm[];
    float*  adjS = sm;
    float*  P_T  = sm + SM_PT;
    float*  whT  = sm + SM_WHT;
    float2* e2S  = (float2*)(sm + SM_E2);

    const int t    = threadIdx.x;
    const int lane = t & 31, warp = t >> 5;
    const int ib = blockIdx.x, js = blockIdx.y;
    const int i_base = ib * TI, j0 = js * JRANGE;

    uint32_t sb    = (uint32_t)__cvta_generic_to_shared(sm);
    uint32_t s_adj = sb;
    uint32_t s_wht = sb + SM_WHT * 4;
    uint32_t s_e2  = sb + SM_E2 * 4;

    const float2 e1 = g_E1P[i_base + t];
    float den = 0.f;
    float acc[4][4][4];
    #pragma unroll
    for (int m = 0; m < 4; m++)
        #pragma unroll
        for (int n = 0; n < 4; n++)
            #pragma unroll
            for (int e = 0; e < 4; e++) acc[m][n][e] = 0.f;

    const float* adj_row = adj + (size_t)(i_base + t) * N + j0;
    const int wf = t >> 2, wc = t & 3;     // whT staging map

    // ---- prologue: prefetch tile 0 ----
    {
        #pragma unroll
        for (int m = 0; m < 8; m++) CP_ASYNC16(s_adj + t * 144 + m * 16, adj_row + m * 4);
        const float* ws = g_WhT + (size_t)wf * N + j0;
        CP_ASYNC16(s_wht + wf * 144 + wc * 16,      ws + wc * 4);
        CP_ASYNC16(s_wht + wf * 144 + 64 + wc * 16, ws + 16 + wc * 4);
        if (t < 16) CP_ASYNC16(s_e2 + t * 16, (const float*)(g_E2P + j0) + t * 4);
        CP_COMMIT();
    }

    for (int it = 0; it < NT; it++) {
        const int pb = it & 1;
        CP_WAIT0();
        __syncthreads();

        // ---- P build: thread t owns row i=t; tf32-rounded; den matches ----
        #pragma unroll
        for (int c4 = 0; c4 < 8; c4++) {
            float4 av = *(float4*)&adjS[t * 36 + c4 * 4];
            float4 pv;
            #pragma unroll
            for (int e = 0; e < 4; e++) {
                float2 e2 = e2S[c4 * 4 + e];
                float p = fmaxf(e1.x * e2.x, e1.y * e2.y) * ((&av.x)[e]);
                p = tf32r(p);
                den += p;
                (&pv.x)[e] = p;
            }
            *(float4*)&P_T[t * 36 + c4 * 4] = pv;
        }
        __syncthreads();

        // ---- prefetch next tile (adj/e2 single-buf, whT double-buf) ----
        if (it + 1 < NT) {
            const float* asrc = adj_row + (it + 1) * TJ;
            #pragma unroll
            for (int m = 0; m < 8; m++) CP_ASYNC16(s_adj + t * 144 + m * 16, asrc + m * 4);
            const float* ws = g_WhT + (size_t)wf * N + j0 + (it + 1) * TJ;
            uint32_t wd = s_wht + (pb ^ 1) * 9216 + wf * 144;
            CP_ASYNC16(wd + wc * 16,      ws + wc * 4);
            CP_ASYNC16(wd + 64 + wc * 16, ws + 16 + wc * 4);
            if (t < 16)
                CP_ASYNC16(s_e2 + t * 16, (const float*)(g_E2P + j0 + (it + 1) * TJ) + t * 4);
            CP_COMMIT();
        }

        // ---- tensor-core GEMM: D[f][i] += Wh^T x P^T ----
        const float* whb = whT + pb * 2304;
        const int r4 = lane >> 2, c4l = lane & 3;
        const float* pB = P_T + (warp * 32 + r4) * 36;

        #pragma unroll
        for (int kt = 0; kt < 4; kt++) {
            uint32_t b0[4], b1[4];
            #pragma unroll
            for (int nt = 0; nt < 4; nt++) {
                b0[nt] = __float_as_uint(pB[nt * 288 + kt * 8 + c4l]);
                b1[nt] = __float_as_uint(pB[nt * 288 + kt * 8 + c4l + 4]);
            }
            #pragma unroll
            for (int mt = 0; mt < 4; mt++) {
                const float* wa = whb + (mt * 16 + r4) * 36 + kt * 8 + c4l;
                uint32_t a0 = __float_as_uint(wa[0]);
                uint32_t a1 = __float_as_uint(wa[8 * 36]);
                uint32_t a2 = __float_as_uint(wa[4]);
                uint32_t a3 = __float_as_uint(wa[8 * 36 + 4]);
                #pragma unroll
                for (int nt = 0; nt < 4; nt++)
                    MMA_TF32(acc[mt][nt], a0, a1, a2, a3, b0[nt], b1[nt]);
            }
        }
    }

    // ---- epilogue: D fragments -> g_acc[js][f][i] ----
    float* ob = g_acc[js];
    #pragma unroll
    for (int mt = 0; mt < 4; mt++) {
        const int f0 = mt * 16 + (lane >> 2);
        #pragma unroll
        for (int nt = 0; nt < 4; nt++) {
            const int i0 = i_base + warp * 32 + nt * 8 + 2 * (lane & 3);
            *(float2*)&ob[(size_t)f0 * N + i0]       = make_float2(acc[mt][nt][0], acc[mt][nt][1]);
            *(float2*)&ob[(size_t)(f0 + 8) * N + i0] = make_float2(acc[mt][nt][2], acc[mt][nt][3]);
        }
    }
    g_den[js][i_base + t] = den;   // full row sum lives in one thread
}

// ============================================================
// Kernel C: combine partials, normalize, ELU, transpose to [i][f].
// 128 blocks x 256 threads; 64-row tile per block.
// ============================================================
__global__ void __launch_bounds__(256) gat_final(float* __restrict__ out)
{
    __shared__ float tS[64 * 68];
    __shared__ float denS[64];
    const int t  = threadIdx.x;
    const int i0 = blockIdx.x * 64;

    if (t < 64) {
        float d = 0.f;
        #pragma unroll
        for (int s = 0; s < JSPLIT; s++) d += g_den[s][i0 + t];
        denS[t] = d;
    }
    __syncthreads();

    const int fi = t >> 4, iq = (t & 15) * 4;
    #pragma unroll
    for (int m = 0; m < 4; m++) {
        const int f = fi + m * 16;
        float4 v = make_float4(0.f, 0.f, 0.f, 0.f);
        #pragma unroll
        for (int s = 0; s < JSPLIT; s++) {
            float4 u = *(const float4*)&g_acc[s][(size_t)f * N + i0 + iq];
            v.x += u.x; v.y += u.y; v.z += u.z; v.w += u.w;
        }
        #pragma unroll
        for (int e = 0; e < 4; e++) {
            float h = (&v.x)[e] / denS[iq + e];
            tS[(iq + e) * 68 + f] = (h > 0.f) ? h : expm1f(h);
        }
    }
    __syncthreads();

    const int r = t >> 2, cq = t & 3;
    #pragma unroll
    for (int q = 0; q < 4; q++) {
        float4 o = *(float4*)&tS[r * 68 + cq * 16 + q * 4];
        *(float4*)&out[(size_t)(i0 + r) * 64 + cq * 16 + q * 4] = o;
    }
}

// ============================================================
extern "C" void kernel_launch(void* const* d_in, const int* in_sizes, int n_in,
                              void* d_out, int out_size)
{
    const float* x   = (const float*)d_in[0];
    const float* adj = (const float*)d_in[1];
    const float* W   = (const float*)d_in[2];
    const float* a   = (const float*)d_in[3];
    float* out = (float*)d_out;

    cudaFuncSetAttribute(gat_attn, cudaFuncAttributeMaxDynamicSharedMemorySize,
                         SMEMB_BYTES);

    gat_prep<<<N / 16, 256>>>(x, W, a);
    gat_attn<<<dim3(N / TI, JSPLIT), 256, SMEMB_BYTES>>>(adj);
    gat_final<<<N / 64, 256>>>(out);
}

// round 4
// speedup vs baseline: 2.9879x; 1.1483x over previous
#include <cuda_runtime.h>
#include <cuda_fp16.h>
#include <cstdint>

// GAT layer, N=8192, Fin=128, Fout=64.
// inputs: x [N,128] f32, adj [N,N] f32 (0/1), W [128,64] f32, a [128,1] f32
// output: [N,64] f32

#define N      8192
#define FOUT   64
#define TI     128
#define TJ     32
#define JSPLIT 16
#define JRANGE (N / JSPLIT)     // 512
#define NT     (JRANGE / TJ)    // 16
#define ADJ_STRIDE 40           // padded floats per adj row (conflict-free LDS.64)

// ---------------- device scratch ----------------
__device__ float2 g_E1P[N];                  // (e^Wh1, e^{0.2 Wh1})
__device__ float2 g_E2P[N];                  // (e^Wh2, e^{0.2 Wh2})
__device__ __half g_WhT_h[FOUT * N];         // Wh^T [f][j], fp16
__device__ float  g_acc[JSPLIT][N * FOUT];   // partial numerators [js][i][f]
__device__ float  g_den[JSPLIT][N];          // partial denominators

// ---------------- helpers ----------------
__device__ __forceinline__ unsigned long long packdup(float v) {
    unsigned long long r;
    asm("mov.b64 %0, {%1, %1};" : "=l"(r) : "f"(v));
    return r;
}
__device__ __forceinline__ float2 unpack2(unsigned long long v) {
    float2 r;
    asm("mov.b64 {%0, %1}, %2;" : "=f"(r.x), "=f"(r.y) : "l"(v));
    return r;
}
#define FFMA2(d, a, b) asm("fma.rn.f32x2 %0, %1, %2, %3;" : "=l"(d) : "l"(a), "l"(b), "l"(d))

#define CP_ASYNC16(dst, src) \
    asm volatile("cp.async.cg.shared.global [%0], [%1], 16;" :: "r"(dst), "l"(src))
#define CP_COMMIT() asm volatile("cp.async.commit_group;")
#define CP_WAIT1()  asm volatile("cp.async.wait_group 1;" ::: "memory")

#define MMA_F16(D, A, B0, B1)                                                 \
    asm("mma.sync.aligned.m16n8k16.row.col.f32.f16.f16.f32 "                  \
        "{%0,%1,%2,%3},{%4,%5,%6,%7},{%8,%9},{%0,%1,%2,%3};"                  \
        : "+f"((D)[0]), "+f"((D)[1]), "+f"((D)[2]), "+f"((D)[3])              \
        : "r"((A)[0]), "r"((A)[1]), "r"((A)[2]), "r"((A)[3]),                 \
          "r"(B0), "r"(B1))

__device__ __forceinline__ uint32_t pack_h2(float a, float b) {
    __half2 h = __float22half2_rn(make_float2(a, b));
    return *reinterpret_cast<uint32_t*>(&h);
}

// ============================================================
// Kernel A: Wh = x@W, attention dots, exp tables, fp16 Wh^T.
// 512 blocks x 256 threads; 16 rows/block, 16 threads/row (4 cols each).
// ============================================================
__global__ void __launch_bounds__(256) gat_prep(const float* __restrict__ x,
                                                const float* __restrict__ W,
                                                const float* __restrict__ a)
{
    __shared__ float wS[128 * 64];
    __shared__ float xS[16 * 128];
    __shared__ float aS[128];
    __shared__ __half tSh[64][20];
    const int t = threadIdx.x;
    const int row0 = blockIdx.x * 16;

    #pragma unroll
    for (int q = 0; q < 8; q++) {
        int idx = (q * 256 + t) * 4;
        *(float4*)&wS[idx] = *(const float4*)&W[idx];
    }
    if (t < 32) *(float4*)&aS[t * 4] = *(const float4*)&a[t * 4];
    #pragma unroll
    for (int q = 0; q < 2; q++) {
        int idx = (q * 256 + t) * 4;
        *(float4*)&xS[idx] = *(const float4*)&x[(size_t)row0 * 128 + idx];
    }
    __syncthreads();

    const int r = t >> 4, c = t & 15;
    unsigned long long acc2[2] = {0ull, 0ull};

    #pragma unroll 16
    for (int kk = 0; kk < 128; kk++) {
        unsigned long long xd = packdup(xS[r * 128 + kk]);
        const unsigned long long* w =
            reinterpret_cast<const unsigned long long*>(&wS[kk * 64 + c * 4]);
        FFMA2(acc2[0], xd, w[0]);
        FFMA2(acc2[1], xd, w[1]);
    }

    float wv[4];
    { float2 u0 = unpack2(acc2[0]), u1 = unpack2(acc2[1]);
      wv[0] = u0.x; wv[1] = u0.y; wv[2] = u1.x; wv[3] = u1.y; }

    float p1 = 0.f, p2 = 0.f;
    #pragma unroll
    for (int e = 0; e < 4; e++) {
        p1 += wv[e] * aS[c * 4 + e];
        p2 += wv[e] * aS[64 + c * 4 + e];
    }
    p1 += __shfl_xor_sync(0xffffffffu, p1, 1);
    p1 += __shfl_xor_sync(0xffffffffu, p1, 2);
    p1 += __shfl_xor_sync(0xffffffffu, p1, 4);
    p1 += __shfl_xor_sync(0xffffffffu, p1, 8);
    p2 += __shfl_xor_sync(0xffffffffu, p2, 1);
    p2 += __shfl_xor_sync(0xffffffffu, p2, 2);
    p2 += __shfl_xor_sync(0xffffffffu, p2, 4);
    p2 += __shfl_xor_sync(0xffffffffu, p2, 8);

    // stage fp16 Wh^T tile through smem for coalesced [f][j] store
    #pragma unroll
    for (int e = 0; e < 4; e++) tSh[c * 4 + e][r] = __float2half(wv[e]);

    const int row = row0 + r;
    if (c == 0) {
        g_E1P[row] = make_float2(__expf(p1), __expf(0.2f * p1));
        g_E2P[row] = make_float2(__expf(p2), __expf(0.2f * p2));
    }
    __syncthreads();

    const int f = t >> 2, seg = t & 3;
    *(uint2*)&g_WhT_h[(size_t)f * N + row0 + seg * 4] =
        *(uint2*)&tSh[f][seg * 4];
}

// ============================================================
// Kernel B: register-built P fragments + fp16 tensor-core GEMM.
// grid (N/TI, JSPLIT) = (64, 16) = 1024 blocks x 128 threads (4 warps).
// Warp w owns i-rows [i_base + w*32, +32): mt=2 (m16), nt=8 (n8), kt=2 (k16).
// Only adj goes through smem (cp.async double buffer).
// ============================================================
#define ADJ_BUF_FLOATS (TI * ADJ_STRIDE)           // 5120
#define SMEMB_BYTES (2 * ADJ_BUF_FLOATS * 4)       // 40960

__global__ void __launch_bounds__(128, 2) gat_attn(const float* __restrict__ adj)
{
    extern __shared__ float adjS[];                 // [2][TI][ADJ_STRIDE]

    const int t    = threadIdx.x;
    const int lane = t & 31, warp = t >> 5;
    const int ib = blockIdx.x, js = blockIdx.y;
    const int i_base = ib * TI;
    const int i_warp = i_base + warp * 32;
    const int j0 = js * JRANGE;

    const int r0 = lane >> 2;          // fragment row within m16
    const int c0 = (lane & 3) * 2;     // fragment k-col pair base

    uint32_t s_adj = (uint32_t)__cvta_generic_to_shared(adjS);
    const float* adj_row = adj + (size_t)(i_base + t) * N + j0;

    // loop-invariant row factors
    float2 e1v[2][2];
    #pragma unroll
    for (int mt = 0; mt < 2; mt++)
        #pragma unroll
        for (int aa = 0; aa < 2; aa++)
            e1v[mt][aa] = g_E1P[i_warp + mt * 16 + aa * 8 + r0];

    float acc[2][8][4];
    #pragma unroll
    for (int mt = 0; mt < 2; mt++)
        #pragma unroll
        for (int nt = 0; nt < 8; nt++)
            #pragma unroll
            for (int e = 0; e < 4; e++) acc[mt][nt][e] = 0.f;
    float den[2][2] = {{0.f, 0.f}, {0.f, 0.f}};

    // prologue: prefetch tiles 0 and 1
    #pragma unroll
    for (int pf = 0; pf < 2; pf++) {
        uint32_t dst = s_adj + pf * (ADJ_BUF_FLOATS * 4) + t * (ADJ_STRIDE * 4);
        const float* src = adj_row + pf * TJ;
        #pragma unroll
        for (int m = 0; m < 8; m++) CP_ASYNC16(dst + m * 16, src + m * 4);
        CP_COMMIT();
    }

    const __half* __restrict__ whp = g_WhT_h;

    for (int it = 0; it < NT; it++) {
        const int buf = it & 1;
        const int jt = j0 + it * TJ;
        CP_WAIT1();
        __syncthreads();

        // ---- B fragments (Wh^T fp16 from global, L1/L2 resident) ----
        uint32_t b[8][2][2];
        #pragma unroll
        for (int nt = 0; nt < 8; nt++)
            #pragma unroll
            for (int kt = 0; kt < 2; kt++)
                #pragma unroll
                for (int hh = 0; hh < 2; hh++)
                    b[nt][kt][hh] = *(const uint32_t*)
                        &whp[(size_t)(nt * 8 + r0) * N + jt + kt * 16 + hh * 8 + c0];

        // ---- column factors ----
        float4 e2q[2][2];
        #pragma unroll
        for (int kt = 0; kt < 2; kt++)
            #pragma unroll
            for (int hh = 0; hh < 2; hh++)
                e2q[kt][hh] = *(const float4*)
                    ((const float*)&g_E2P[jt + kt * 16 + hh * 8 + c0]);

        // ---- build A fragments (P) directly in registers ----
        uint32_t afr[2][2][4];
        #pragma unroll
        for (int mt = 0; mt < 2; mt++) {
            #pragma unroll
            for (int kt = 0; kt < 2; kt++) {
                #pragma unroll
                for (int aa = 0; aa < 2; aa++) {
                    float2 e1 = e1v[mt][aa];
                    const int R = warp * 32 + mt * 16 + aa * 8 + r0;
                    #pragma unroll
                    for (int hh = 0; hh < 2; hh++) {
                        float2 ad = *(float2*)&adjS[buf * ADJ_BUF_FLOATS +
                                                    R * ADJ_STRIDE +
                                                    kt * 16 + hh * 8 + c0];
                        float4 q = e2q[kt][hh];
                        float p0 = fmaxf(e1.x * q.x, e1.y * q.y) * ad.x;
                        float p1 = fmaxf(e1.x * q.z, e1.y * q.w) * ad.y;
                        den[mt][aa] += p0 + p1;
                        afr[mt][kt][aa + 2 * hh] = pack_h2(p0, p1);
                    }
                }
            }
        }
        __syncthreads();   // all warps done reading buf

        // ---- prefetch tile it+2 into buf ----
        if (it + 2 < NT) {
            uint32_t dst = s_adj + buf * (ADJ_BUF_FLOATS * 4) + t * (ADJ_STRIDE * 4);
            const float* src = adj_row + (it + 2) * TJ;
            #pragma unroll
            for (int m = 0; m < 8; m++) CP_ASYNC16(dst + m * 16, src + m * 4);
        }
        CP_COMMIT();       // always commit (possibly empty group) to keep count in step

        // ---- 32 MMAs ----
        #pragma unroll
        for (int mt = 0; mt < 2; mt++)
            #pragma unroll
            for (int nt = 0; nt < 8; nt++) {
                MMA_F16(acc[mt][nt], afr[mt][0], b[nt][0][0], b[nt][0][1]);
                MMA_F16(acc[mt][nt], afr[mt][1], b[nt][1][0], b[nt][1][1]);
            }
    }

    // ---- epilogue: C fragments -> g_acc[js][i][f] ----
    float* ob = g_acc[js];
    #pragma unroll
    for (int mt = 0; mt < 2; mt++) {
        const int ir = i_warp + mt * 16 + r0;
        #pragma unroll
        for (int nt = 0; nt < 8; nt++) {
            const int fc = nt * 8 + c0;
            *(float2*)&ob[(size_t)ir * FOUT + fc] =
                make_float2(acc[mt][nt][0], acc[mt][nt][1]);
            *(float2*)&ob[(size_t)(ir + 8) * FOUT + fc] =
                make_float2(acc[mt][nt][2], acc[mt][nt][3]);
        }
    }
    // den: reduce across the 4 lanes sharing a row
    #pragma unroll
    for (int mt = 0; mt < 2; mt++)
        #pragma unroll
        for (int aa = 0; aa < 2; aa++) {
            float d = den[mt][aa];
            d += __shfl_xor_sync(0xffffffffu, d, 1);
            d += __shfl_xor_sync(0xffffffffu, d, 2);
            if ((lane & 3) == 0)
                g_den[js][i_warp + mt * 16 + aa * 8 + r0] = d;
        }
}

// ============================================================
// Kernel C: combine partials, normalize, ELU.
// ============================================================
__global__ void __launch_bounds__(256) gat_final(float* __restrict__ out)
{
    const int idx = blockIdx.x * 256 + threadIdx.x;   // < N*FOUT
    const int i = idx >> 6;
    float d = 0.f, v = 0.f;
    #pragma unroll
    for (int s = 0; s < JSPLIT; s++) {
        d += g_den[s][i];
        v += g_acc[s][idx];
    }
    float h = v / d;
    out[idx] = (h > 0.f) ? h : expm1f(h);
}

// ============================================================
extern "C" void kernel_launch(void* const* d_in, const int* in_sizes, int n_in,
                              void* d_out, int out_size)
{
    const float* x   = (const float*)d_in[0];
    const float* adj = (const float*)d_in[1];
    const float* W   = (const float*)d_in[2];
    const float* a   = (const float*)d_in[3];
    float* out = (float*)d_out;

    cudaFuncSetAttribute(gat_attn, cudaFuncAttributeMaxDynamicSharedMemorySize,
                         SMEMB_BYTES);

    gat_prep<<<N / 16, 256>>>(x, W, a);
    gat_attn<<<dim3(N / TI, JSPLIT), TI, SMEMB_BYTES>>>(adj);
    gat_final<<<(N * FOUT) / 256, 256>>>(out);
}

// round 5
// speedup vs baseline: 3.3484x; 1.1207x over previous
#include <cuda_runtime.h>
#include <cuda_fp16.h>
#include <cstdint>

// GAT layer, N=8192, Fin=128, Fout=64.
// inputs: x [N,128] f32, adj [N,N] f32 (0/1), W [128,64] f32, a [128,1] f32
// output: [N,64] f32

#define N      8192
#define FOUT   64
#define TI     128
#define TJ     32
#define JSPLIT 16
#define JRANGE (N / JSPLIT)     // 512
#define NT     (JRANGE / TJ)    // 16

#define ADJ_STR 36              // floats per adj smem row (144 B)
#define WH_STR  72              // halves per Wh smem row (144 B)
#define STAGE_ADJ_B (TI * ADJ_STR * 4)   // 18432
#define STAGE_WH_B  (TJ * WH_STR * 2)    //  4608
#define STAGE_B     (STAGE_ADJ_B + STAGE_WH_B)  // 23040
#define NSTAGE 4
#define SMEMB_BYTES (NSTAGE * STAGE_B)   // 92160

// ---------------- device scratch ----------------
__device__ float2 g_E1P[N];                  // (e^Wh1, e^{0.2 Wh1}) fp32
__device__ __half g_E2XH[N];                 // fp16 e^Wh2
__device__ __half g_E2YH[N];                 // fp16 e^{0.2 Wh2}
__device__ __half g_Wh_h[N * FOUT];          // Wh [j][f] fp16
__device__ float  g_acc[JSPLIT][N * FOUT];   // partial numerators [js][i][f]
__device__ float  g_den[JSPLIT][N];          // partial denominators

// ---------------- helpers ----------------
__device__ __forceinline__ unsigned long long packdup(float v) {
    unsigned long long r;
    asm("mov.b64 %0, {%1, %1};" : "=l"(r) : "f"(v));
    return r;
}
__device__ __forceinline__ float2 unpack2(unsigned long long v) {
    float2 r;
    asm("mov.b64 {%0, %1}, %2;" : "=f"(r.x), "=f"(r.y) : "l"(v));
    return r;
}
#define FFMA2(d, a, b) asm("fma.rn.f32x2 %0, %1, %2, %3;" : "=l"(d) : "l"(a), "l"(b), "l"(d))

#define CP_ASYNC16(dst, src) \
    asm volatile("cp.async.cg.shared.global [%0], [%1], 16;" :: "r"(dst), "l"(src))
#define CP_COMMIT() asm volatile("cp.async.commit_group;")
#define CP_WAIT2()  asm volatile("cp.async.wait_group 2;" ::: "memory")

#define LDSM_X4_T(d0, d1, d2, d3, addr)                                        \
    asm volatile("ldmatrix.sync.aligned.m8n8.x4.trans.shared.b16 "             \
                 "{%0,%1,%2,%3}, [%4];"                                        \
                 : "=r"(d0), "=r"(d1), "=r"(d2), "=r"(d3) : "r"(addr))

#define MMA_F16(D, A, B0, B1)                                                 \
    asm("mma.sync.aligned.m16n8k16.row.col.f32.f16.f16.f32 "                  \
        "{%0,%1,%2,%3},{%4,%5,%6,%7},{%8,%9},{%0,%1,%2,%3};"                  \
        : "+f"((D)[0]), "+f"((D)[1]), "+f"((D)[2]), "+f"((D)[3])              \
        : "r"((A)[0]), "r"((A)[1]), "r"((A)[2]), "r"((A)[3]),                 \
          "r"(B0), "r"(B1))

// ============================================================
// Kernel A: Wh = x@W, attention dots, exp tables (fp16), Wh fp16 [j][f].
// 128 blocks x 512 threads; 64 rows/block, 8 threads/row.
// Thread (r, c): owns column pairs {16m + 2c, 16m + 2c + 1}, m=0..3.
// Dyn smem: wS f32[8192] | xS f32[64*132] | aS f32[128]  = 67072 B
// ============================================================
#define XSTR 132
#define PREP_SMEM ((8192 + 64 * XSTR + 128) * 4)

__global__ void __launch_bounds__(512) gat_prep(const float* __restrict__ x,
                                                const float* __restrict__ W,
                                                const float* __restrict__ a)
{
    extern __shared__ float psm[];
    float* wS = psm;                  // [128][64]
    float* xS = psm + 8192;           // [64][XSTR]
    float* aS = psm + 8192 + 64 * XSTR;

    const int t = threadIdx.x;
    const int row0 = blockIdx.x * 64;

    #pragma unroll
    for (int q = 0; q < 4; q++) {
        int idx = (q * 512 + t) * 4;
        *(float4*)&wS[idx] = *(const float4*)&W[idx];
    }
    const float* xb = x + (size_t)row0 * 128;
    #pragma unroll
    for (int q = 0; q < 4; q++) {
        int flat = (q * 512 + t) * 4;
        int r = flat >> 7, c = flat & 127;
        *(float4*)&xS[r * XSTR + c] = *(const float4*)&xb[flat];
    }
    if (t < 32) *(float4*)&aS[t * 4] = *(const float4*)&a[t * 4];
    __syncthreads();

    const int r = t >> 3, c = t & 7;
    unsigned long long acc4[4] = {0ull, 0ull, 0ull, 0ull};

    #pragma unroll 8
    for (int kk = 0; kk < 128; kk++) {
        unsigned long long xd = packdup(xS[r * XSTR + kk]);
        const unsigned long long* w =
            reinterpret_cast<const unsigned long long*>(&wS[kk * 64]);
        FFMA2(acc4[0], xd, w[c]);
        FFMA2(acc4[1], xd, w[8 + c]);
        FFMA2(acc4[2], xd, w[16 + c]);
        FFMA2(acc4[3], xd, w[24 + c]);
    }

    float p1 = 0.f, p2 = 0.f;
    const int row = row0 + r;
    #pragma unroll
    for (int m = 0; m < 4; m++) {
        float2 u = unpack2(acc4[m]);
        const int col = 16 * m + 2 * c;
        p1 += u.x * aS[col]      + u.y * aS[col + 1];
        p2 += u.x * aS[64 + col] + u.y * aS[64 + col + 1];
        *(__half2*)&g_Wh_h[(size_t)row * 64 + col] = __floats2half2_rn(u.x, u.y);
    }
    p1 += __shfl_xor_sync(0xffffffffu, p1, 1);
    p1 += __shfl_xor_sync(0xffffffffu, p1, 2);
    p1 += __shfl_xor_sync(0xffffffffu, p1, 4);
    p2 += __shfl_xor_sync(0xffffffffu, p2, 1);
    p2 += __shfl_xor_sync(0xffffffffu, p2, 2);
    p2 += __shfl_xor_sync(0xffffffffu, p2, 4);

    if (c == 0) {
        g_E1P[row]  = make_float2(__expf(p1), __expf(0.2f * p1));
        g_E2XH[row] = __float2half(__expf(p2));
        g_E2YH[row] = __float2half(__expf(0.2f * p2));
    }
}

// ============================================================
// Kernel B: half2 P-fragments + ldmatrix B + fp16 MMA + den-by-MMA.
// grid (64, 16) x 128 threads (4 warps). 4-stage cp.async pipeline.
// Stage: [adj 128x36 f32][Wh 32x72 fp16].
// ============================================================
__global__ void __launch_bounds__(128, 2) gat_attn(const float* __restrict__ adj)
{
    extern __shared__ char smem[];
    const int t = threadIdx.x, lane = t & 31, warp = t >> 5;
    const int ib = blockIdx.x, js = blockIdx.y;
    const int i_base = ib * TI, i_warp = i_base + warp * 32;
    const int j0 = js * JRANGE;
    const int r0 = lane >> 2, c0 = (lane & 3) * 2;

    const uint32_t sb = (uint32_t)__cvta_generic_to_shared(smem);
    const float* adj_row = adj + (size_t)(i_base + t) * N + j0;

    // e1 fp16 splats (invariant)
    __half2 e1x2[2][2], e1y2[2][2];
    #pragma unroll
    for (int mt = 0; mt < 2; mt++)
        #pragma unroll
        for (int aa = 0; aa < 2; aa++) {
            float2 e1f = g_E1P[i_warp + mt * 16 + aa * 8 + r0];
            e1x2[mt][aa] = __half2half2(__float2half(e1f.x));
            e1y2[mt][aa] = __half2half2(__float2half(e1f.y));
        }

    float acc[2][8][4];
    float accden[2][4];
    #pragma unroll
    for (int mt = 0; mt < 2; mt++) {
        #pragma unroll
        for (int nt = 0; nt < 8; nt++)
            #pragma unroll
            for (int e = 0; e < 4; e++) acc[mt][nt][e] = 0.f;
        #pragma unroll
        for (int e = 0; e < 4; e++) accden[mt][e] = 0.f;
    }
    const uint32_t bones = (r0 == 0) ? 0x3C003C00u : 0u;   // ones column (fp16 1.0)

    // ldmatrix lane addressing (x4.trans): lane -> (matrix m, row)
    const int mm = lane >> 3;
    const int ldsm_row = (mm & 1) * 8 + (lane & 7);   // j-row within 16
    const int ldsm_f   = mm >> 1;                     // f-octet parity

    // staging maps
    const int wrow0 = t >> 3,          wseg0 = t & 7;          // chunk t
    const int wrow1 = (t + 128) >> 3,  wseg1 = t & 7;          // chunk t+128

#define PREFETCH(tt)                                                           \
    do {                                                                       \
        const int s_ = (tt) & 3;                                               \
        const uint32_t ab_ = sb + s_ * STAGE_B;                                \
        const float* asrc_ = adj_row + (tt) * TJ;                              \
        _Pragma("unroll")                                                      \
        for (int m_ = 0; m_ < 8; m_++)                                         \
            CP_ASYNC16(ab_ + t * (ADJ_STR * 4) + m_ * 16, asrc_ + m_ * 4);     \
        const uint32_t wb_ = ab_ + STAGE_ADJ_B;                                \
        const __half* ws0_ = g_Wh_h + (size_t)(j0 + (tt) * TJ + wrow0) * 64 + wseg0 * 8; \
        const __half* ws1_ = g_Wh_h + (size_t)(j0 + (tt) * TJ + wrow1) * 64 + wseg1 * 8; \
        CP_ASYNC16(wb_ + wrow0 * (WH_STR * 2) + wseg0 * 16, ws0_);             \
        CP_ASYNC16(wb_ + wrow1 * (WH_STR * 2) + wseg1 * 16, ws1_);             \
        CP_COMMIT();                                                           \
    } while (0)

    PREFETCH(0); PREFETCH(1); PREFETCH(2);

    #pragma unroll 1
    for (int it = 0; it < NT; it++) {
        const int s = it & 3;
        const int jt = j0 + it * TJ;
        CP_WAIT2();
        __syncthreads();
        if (it + 3 < NT) { PREFETCH(it + 3); } else { CP_COMMIT(); }

        const uint32_t wb = sb + s * STAGE_B + STAGE_ADJ_B;
        const float* adjS = (const float*)(smem + s * STAGE_B);

        // ---- B fragments via ldmatrix.x4.trans ----
        uint32_t b[8][2][2];
        #pragma unroll
        for (int kt = 0; kt < 2; kt++) {
            const uint32_t abase = wb + (kt * 16 + ldsm_row) * (WH_STR * 2) + ldsm_f * 16;
            #pragma unroll
            for (int p = 0; p < 4; p++) {
                uint32_t q0, q1, q2, q3;
                LDSM_X4_T(q0, q1, q2, q3, abase + p * 32);
                b[2 * p][kt][0] = q0; b[2 * p][kt][1] = q1;
                b[2 * p + 1][kt][0] = q2; b[2 * p + 1][kt][1] = q3;
            }
        }

        // ---- e2 fp16 pair loads (L1-hot) ----
        __half2 ex2[2][2], ey2[2][2];
        #pragma unroll
        for (int kt = 0; kt < 2; kt++)
            #pragma unroll
            for (int hh = 0; hh < 2; hh++) {
                const int jj = jt + kt * 16 + hh * 8 + c0;
                ex2[kt][hh] = *(const __half2*)&g_E2XH[jj];
                ey2[kt][hh] = *(const __half2*)&g_E2YH[jj];
            }

        // ---- A fragments (P) in half2 ----
        uint32_t afr[2][2][4];
        #pragma unroll
        for (int mt = 0; mt < 2; mt++)
            #pragma unroll
            for (int kt = 0; kt < 2; kt++)
                #pragma unroll
                for (int aa = 0; aa < 2; aa++) {
                    const int R = warp * 32 + mt * 16 + aa * 8 + r0;
                    #pragma unroll
                    for (int hh = 0; hh < 2; hh++) {
                        float2 ad = *(const float2*)&adjS[R * ADJ_STR + kt * 16 + hh * 8 + c0];
                        __half2 ah = __floats2half2_rn(ad.x, ad.y);
                        __half2 u  = __hmul2(e1x2[mt][aa], ex2[kt][hh]);
                        __half2 v  = __hmul2(e1y2[mt][aa], ey2[kt][hh]);
                        __half2 p  = __hmul2(__hmax2(u, v), ah);
                        afr[mt][kt][aa + 2 * hh] = *(uint32_t*)&p;
                    }
                }

        // ---- MMAs (incl. den column) ----
        #pragma unroll
        for (int mt = 0; mt < 2; mt++) {
            #pragma unroll
            for (int nt = 0; nt < 8; nt++) {
                MMA_F16(acc[mt][nt], afr[mt][0], b[nt][0][0], b[nt][0][1]);
                MMA_F16(acc[mt][nt], afr[mt][1], b[nt][1][0], b[nt][1][1]);
            }
            MMA_F16(accden[mt], afr[mt][0], bones, bones);
            MMA_F16(accden[mt], afr[mt][1], bones, bones);
        }
    }

    // ---- epilogue ----
    float* ob = g_acc[js];
    #pragma unroll
    for (int mt = 0; mt < 2; mt++) {
        const int ir = i_warp + mt * 16 + r0;
        #pragma unroll
        for (int nt = 0; nt < 8; nt++) {
            const int fc = nt * 8 + c0;
            *(float2*)&ob[(size_t)ir * FOUT + fc] =
                make_float2(acc[mt][nt][0], acc[mt][nt][1]);
            *(float2*)&ob[(size_t)(ir + 8) * FOUT + fc] =
                make_float2(acc[mt][nt][2], acc[mt][nt][3]);
        }
    }
    if ((lane & 3) == 0) {
        #pragma unroll
        for (int mt = 0; mt < 2; mt++) {
            g_den[js][i_warp + mt * 16 + r0]     = accden[mt][0];
            g_den[js][i_warp + mt * 16 + 8 + r0] = accden[mt][2];
        }
    }
}

// ============================================================
// Kernel C: combine partials, normalize, ELU.
// ============================================================
__global__ void __launch_bounds__(256) gat_final(float* __restrict__ out)
{
    const int idx = blockIdx.x * 256 + threadIdx.x;   // < N*FOUT
    const int i = idx >> 6;
    float d = 0.f, v = 0.f;
    #pragma unroll
    for (int s = 0; s < JSPLIT; s++) {
        d += g_den[s][i];
        v += g_acc[s][idx];
    }
    float h = v / d;
    out[idx] = (h > 0.f) ? h : expm1f(h);
}

// ============================================================
extern "C" void kernel_launch(void* const* d_in, const int* in_sizes, int n_in,
                              void* d_out, int out_size)
{
    const float* x   = (const float*)d_in[0];
    const float* adj = (const float*)d_in[1];
    const float* W   = (const float*)d_in[2];
    const float* a   = (const float*)d_in[3];
    float* out = (float*)d_out;

    cudaFuncSetAttribute(gat_prep, cudaFuncAttributeMaxDynamicSharedMemorySize,
                         PREP_SMEM);
    cudaFuncSetAttribute(gat_attn, cudaFuncAttributeMaxDynamicSharedMemorySize,
                         SMEMB_BYTES);

    gat_prep<<<N / 64, 512, PREP_SMEM>>>(x, W, a);
    gat_attn<<<dim3(N / TI, JSPLIT), TI, SMEMB_BYTES>>>(adj);
    gat_final<<<(N * FOUT) / 256, 256>>>(out);
}